// round 15
// baseline (speedup 1.0000x reference)
#include <cuda_runtime.h>

// Problem constants (match reference)
#define NUM_CH   5
#define CROP_LO  70      // D//2 - 16, D = 173
#define CROP_HI  101     // CROP_LO + 32 - 1
#define CROP_N   32
#define CUBES    5
#define LATO     11      // 2*CUBES+1
#define RES2     0.0625f // RES*RES

#define SLABS    3       // x-slabs of width 11,11,10 -> 40*3 = 120 blocks
#define MAXA     64      // atoms per batch (fixed problem shape)

// ONE kernel, one node, 120 blocks x 256 threads, ONE __syncthreads.
// Block exclusively owns a (batch, channel, x-slab) region. Atom params go to
// FIXED slots (slot = atom id, no atomic compaction); validity via two warp
// ballots in smem; phase 2 bit-walks the masks and splats cell-parallel
// across all 256 threads (<=6 inner iterations per atom).
__global__ void __launch_bounds__(256) fused_voxelize_kernel(
    const float* __restrict__ coords,        // [B, N, 3]
    const int*   __restrict__ atoms_channel, // [B, N]
    const float* __restrict__ radius,        // [B, N]
    float* __restrict__ out,                 // [B, NUM_CH, 32, 32, 32]
    int n_per_batch)
{
    __shared__ float4   s_f[MAXA];    // fx, fy, fz, coef
    __shared__ int4     s_i[MAXA];    // ntot, nyz, nz, offset
    __shared__ float2   s_r[MAXA];    // rnyz, rnz
    __shared__ unsigned s_mask[2];    // validity ballots for atoms 0-31, 32-63

    const int tid  = threadIdx.x;
    const int bc   = blockIdx.x;          // b * NUM_CH + ch  (0..39)
    const int slab = blockIdx.y;          // 0..2
    const int b    = bc / NUM_CH;
    const int ch   = bc - b * NUM_CH;

    const int xs    = slab * 11;                    // slab x start (crop coords)
    const int xw    = (slab == 2) ? 10 : 11;        // slab width
    const int sx_lo = CROP_LO + xs;
    const int sx_hi = sx_lo + xw - 1;

    // --- phase 1a: preload (threads 0..63), loads issue up-front ---
    float cx = 0.f, cy = 0.f, cz = 0.f, r = 1.f;
    int   c  = -1;
    const bool is_loader = (tid < MAXA);
    if (is_loader && tid < n_per_batch) {
        const int atom = b * n_per_batch + tid;
        cx = coords[3 * atom + 0];
        cy = coords[3 * atom + 1];
        cz = coords[3 * atom + 2];
        r  = radius[atom];
        c  = atoms_channel[atom];
    }

    // --- phase 1b: zero this block's exclusive slab (overlaps load latency) ---
    float* vol = out + (size_t)bc * (CROP_N * CROP_N * CROP_N);
    float4* dst = (float4*)(vol + xs * (CROP_N * CROP_N));
    const int n4 = xw * (CROP_N * CROP_N / 4);      // 2816 or 2560
    for (int i = tid; i < n4; i += 256)
        dst[i] = make_float4(0.f, 0.f, 0.f, 0.f);

    // --- phase 1c: derive into FIXED slot tid; ballot validity ---
    bool valid = false;
    if (is_loader) {
        if (c == ch) {
            // scaled = (c + BOX)/RES + (CUBES+1); /0.25 == *4 exactly
            const float sx = (cx + 20.0f) * 4.0f + 6.0f;
            const float sy = (cy + 20.0f) * 4.0f + 6.0f;
            const float sz = (cz + 20.0f) * 4.0f + 6.0f;
            const int bx = (int)floorf(sx) - CUBES;
            const int by = (int)floorf(sy) - CUBES;
            const int bz = (int)floorf(sz) - CUBES;

            const int x0 = max(0, sx_lo  - bx), x1 = min(LATO - 1, sx_hi  - bx);
            const int y0 = max(0, CROP_LO - by), y1 = min(LATO - 1, CROP_HI - by);
            const int z0 = max(0, CROP_LO - bz), z1 = min(LATO - 1, CROP_HI - bz);
            const int nx = x1 - x0 + 1, ny = y1 - y0 + 1, nz = z1 - z0 + 1;

            if (nx > 0 && ny > 0 && nz > 0) {
                valid = true;
                const int nyz = ny * nz;
                s_f[tid] = make_float4(sx - (float)(bx + x0) - 0.5f,
                                       sy - (float)(by + y0) - 0.5f,
                                       sz - (float)(bz + z0) - 0.5f,
                                       0.5f * RES2 / (r * r));
                s_i[tid] = make_int4(nx * nyz, nyz, nz,
                                     ((bx + x0 - CROP_LO) * CROP_N + (by + y0 - CROP_LO)) * CROP_N
                                      + (bz + z0 - CROP_LO));
                s_r[tid] = make_float2(1.0f / (float)nyz, 1.0f / (float)nz);
            }
        }
    }
    if (tid < 64) {
        const unsigned m = __ballot_sync(0xffffffffu, valid);
        if ((tid & 31) == 0) s_mask[tid >> 5] = m;
    }

    __syncthreads();   // one barrier: slots + masks + zeros ordered before splat

    // --- phase 2: bit-walk worklist, cell-parallel splat over 256 threads ---
    #pragma unroll
    for (int w = 0; w < 2; ++w) {
        unsigned m = s_mask[w];
        while (m) {
            const int slot = (w << 5) + (__ffs(m) - 1);
            m &= m - 1;
            const float4 f  = s_f[slot];
            const int4   ii = s_i[slot];
            const float2 rr = s_r[slot];
            const int   ntot = ii.x, nyz = ii.y, nz = ii.z;
            float* __restrict__ p = vol + ii.w;

            for (int k = tid; k < ntot; k += 256) {
                // exact small-int division via fp32 (k < 1331, divisors <= 121)
                int ox  = (int)(((float)k + 0.5f) * rr.x);
                int rem = k - ox * nyz;
                int oy  = (int)(((float)rem + 0.5f) * rr.y);
                int oz  = rem - oy * nz;
                float dx = f.x - (float)ox;
                float dy = f.y - (float)oy;
                float dz = f.z - (float)oz;
                float d2 = fmaf(dx, dx, fmaf(dy, dy, dz * dz));
                float v  = __expf(-f.w * d2);
                atomicAdd(&p[(ox * CROP_N + oy) * CROP_N + oz], v);
            }
        }
    }
}

extern "C" void kernel_launch(void* const* d_in, const int* in_sizes, int n_in,
                              void* d_out, int out_size) {
    const float* coords        = (const float*)d_in[0]; // [B,N,3]
    const int*   atoms_channel = (const int*)d_in[1];   // [B,N]
    const float* radius        = (const float*)d_in[2]; // [B,N]
    float* out = (float*)d_out;

    int n_atoms = in_sizes[1];                               // B*N = 512
    int B = out_size / (NUM_CH * CROP_N * CROP_N * CROP_N);  // 8
    int n_per_batch = n_atoms / B;                           // 64 (<= MAXA)

    dim3 grid(B * NUM_CH, SLABS);                            // 40 x 3 = 120 blocks
    fused_voxelize_kernel<<<grid, 256>>>(coords, atoms_channel, radius, out,
                                         n_per_batch);
}